// round 7
// baseline (speedup 1.0000x reference)
#include <cuda_runtime.h>
#include <cstdint>

// Problem constants (fixed by the reference):
//   BATCH*SEQ = 65536 tokens, HIDDEN = 768, 8 hashes x 16384 buckets x 96-float shards.
#define NUM_HASHES   8
#define NUM_BUCKETS  16384
#define SHARD        96
#define HIDDEN       768
#define LN_EPS       1e-6f

// Primes {31,43,59,61,73,97,103,113} packed as little-endian bytes.
#define PACKED_PRIMES 0x716761493D3B2B1Full

// One warp per token, TWO passes over the gathers:
//   pass 1: gather + accumulate sum/sumsq (values discarded -> no 24-reg array)
//   pass 2: re-gather (L1-hit: 3KB/warp working set) + normalize + store.
// This cuts the register footprint so more warps fit per SM, raising the
// aggregate MLP on the long-latency first-touch gathers.
__global__ __launch_bounds__(256, 6) void canine_emb_ln_kernel(
    const void*      __restrict__ ids_raw, // [n_tokens] int32 OR int64
    const float*     __restrict__ tables,  // [8, 16384, 96] f32
    const float*     __restrict__ ln_scale,// [768]
    const float*     __restrict__ ln_bias, // [768]
    float*           __restrict__ out,     // [n_tokens, 768]
    int n_tokens)
{
    const int warp = (blockIdx.x * blockDim.x + threadIdx.x) >> 5;
    const int lane = threadIdx.x & 31;
    if (warp >= n_tokens) return;

    // --- dtype detect: 32 aligned u64 words of the prefix (256B, in-bounds
    // for both interpretations; L1-hot broadcast). True int64 ids < 2^32 have
    // zero high words; packed int32 pairs have random nonzero high words.
    // (JAX with x64 disabled silently downgrades jnp.int64 randint to int32.)
    const unsigned long long probe =
        ((const unsigned long long*)ids_raw)[lane];
    const bool is64 = !__any_sync(0xFFFFFFFFu, probe > 0xFFFFFFFFull);

    // ids in [0, 1114112): (id+1)*prime fits in int32, result non-negative.
    int id;
    if (is64) id = (int)((const long long*)ids_raw)[warp];
    else      id = ((const int*)ids_raw)[warp];
    const int idp = id + 1;

    // Lane l owns the bucket for hash (l & 7); gathers fetch it via shuffle.
    const int my_prime  = (int)((PACKED_PRIMES >> ((lane & 7) * 8)) & 0xFF);
    const int my_bucket = (idp * my_prime) & (NUM_BUCKETS - 1);

    // float4 index j = lane + 32*k in [0,192); hash shard h = j/24
    // (24 float4s per shard; reference puts hash h at columns [96h,96h+96)).
    // Table float4 index: h*393216 + bucket*24 + (j-24h) = h*393192 + bkt*24 + j.
    const float4* t4 = reinterpret_cast<const float4*>(tables);

    // ---- pass 1: gather + accumulate (values not kept) ----
    float s = 0.f, ss = 0.f;
#pragma unroll
    for (int k = 0; k < 6; k++) {
        const int j   = lane + 32 * k;
        const int h   = j / 24;
        const int bkt = __shfl_sync(0xFFFFFFFFu, my_bucket, h);
        const float4 v = __ldg(t4 + ((size_t)h * 393192 + (size_t)bkt * 24 + j));
        s  += v.x + v.y + v.z + v.w;
        ss += v.x * v.x + v.y * v.y + v.z * v.z + v.w * v.w;
    }
#pragma unroll
    for (int d = 16; d > 0; d >>= 1) {
        s  += __shfl_xor_sync(0xFFFFFFFFu, s,  d);
        ss += __shfl_xor_sync(0xFFFFFFFFu, ss, d);
    }

    const float inv_n = 1.0f / (float)HIDDEN;
    const float mean  = s * inv_n;
    const float var   = fmaxf(ss * inv_n - mean * mean, 0.0f);
    const float rstd  = rsqrtf(var + LN_EPS);

    // ---- pass 2: re-gather (L1 hits), normalize + affine, streaming store ----
    // __stcs keeps the 201MB output stream from evicting the L2-resident
    // tables, which pass-2 reloads (and other warps' pass-1 gathers) rely on.
    const float4* sc4 = reinterpret_cast<const float4*>(ln_scale);
    const float4* bi4 = reinterpret_cast<const float4*>(ln_bias);
    float4* o4 = reinterpret_cast<float4*>(out + (size_t)warp * HIDDEN);

#pragma unroll
    for (int k = 0; k < 6; k++) {
        const int j   = lane + 32 * k;
        const int h   = j / 24;
        const int bkt = __shfl_sync(0xFFFFFFFFu, my_bucket, h);
        const float4 v = __ldg(t4 + ((size_t)h * 393192 + (size_t)bkt * 24 + j));
        const float4 sc = __ldg(sc4 + j);
        const float4 bi = __ldg(bi4 + j);
        float4 r;
        r.x = (v.x - mean) * rstd * sc.x + bi.x;
        r.y = (v.y - mean) * rstd * sc.y + bi.y;
        r.z = (v.z - mean) * rstd * sc.z + bi.z;
        r.w = (v.w - mean) * rstd * sc.w + bi.w;
        __stcs(o4 + j, r);
    }
}

extern "C" void kernel_launch(void* const* d_in, const int* in_sizes, int n_in,
                              void* d_out, int out_size)
{
    const void*  ids    = d_in[0];                 // int32 or int64 input_ids
    const float* tables = (const float*)d_in[1];   // [8,16384,96]
    const float* scale  = (const float*)d_in[2];   // [768]
    const float* bias   = (const float*)d_in[3];   // [768]
    float*       out    = (float*)d_out;

    const int n_tokens = in_sizes[0];              // BATCH*SEQ = 65536
    const int warps_per_block = 256 / 32;          // 8 warps/block
    const int blocks = (n_tokens + warps_per_block - 1) / warps_per_block;
    canine_emb_ln_kernel<<<blocks, 256>>>(ids, tables, scale, bias, out, n_tokens);
}